// round 8
// baseline (speedup 1.0000x reference)
#include <cuda_runtime.h>
#include <cuda_fp16.h>
#include <cstdint>

#define NT 1024
#define NH 2048
#define NI 2048
#define NEXP 16
#define NTOP 4
#define NSLOT (NT*NTOP)
#define NBLKS 64
#define ALPHA 1.702f
#define FLIMIT 7.0f
#define NCH 32               // K chunks of 64 halves

#define STRB 144             // bytes per smem row (128B data + 16B pad)
#define ABYTES (128*STRB)    // 18432
#define STAGEB (2*ABYTES)    // 36864 per stage (A+B)
#define DSMEM_BYTES (2*STAGEB)  // 73728

// ---------------- scratch ----------------
__device__ int    g_tok_exp[NSLOT];
__device__ float  g_tok_w[NSLOT];
__device__ int    g_counts[NEXP];
__device__ int    g_offsets[NEXP];
__device__ int    g_token_list[NSLOT];
__device__ int    g_slot_of[NSLOT];
__device__ __half g_xh[(size_t)NT * NH];       // fp16 x
__device__ __half g_hbuf[(size_t)NSLOT * NI];  // fp16 h
__device__ float  g_obuf[(size_t)NSLOT * NH];

// ---------------- helpers ----------------
__device__ __forceinline__ uint32_t f2h2(float a, float b){
    __half2 h = __floats2half2_rn(a, b);
    return *(uint32_t*)&h;
}
__device__ __forceinline__ uint32_t smem_u32(const void* p){
    uint32_t a;
    asm("{ .reg .u64 t; cvta.to.shared.u64 t, %1; cvt.u32.u64 %0, t; }" : "=r"(a) : "l"(p));
    return a;
}
__device__ __forceinline__ void cp16(uint32_t dst, const void* src){
    asm volatile("cp.async.cg.shared.global [%0], [%1], 16;" :: "r"(dst), "l"(src) : "memory");
}
__device__ __forceinline__ void cp_commit(){ asm volatile("cp.async.commit_group;" ::: "memory"); }
__device__ __forceinline__ void cp_wait0(){ asm volatile("cp.async.wait_group 0;" ::: "memory"); }

__device__ __forceinline__ void ldsm4(uint32_t& r0, uint32_t& r1, uint32_t& r2, uint32_t& r3, uint32_t addr){
    asm volatile("ldmatrix.sync.aligned.m8n8.x4.shared.b16 {%0,%1,%2,%3}, [%4];"
        : "=r"(r0), "=r"(r1), "=r"(r2), "=r"(r3) : "r"(addr));
}
__device__ __forceinline__ void mma_f16(float d[4], const uint32_t a[4], const uint32_t b[2]){
    asm volatile("mma.sync.aligned.m16n8k16.row.col.f32.f16.f16.f32 "
        "{%0,%1,%2,%3},{%4,%5,%6,%7},{%8,%9},{%0,%1,%2,%3};"
        : "+f"(d[0]),"+f"(d[1]),"+f"(d[2]),"+f"(d[3])
        : "r"(a[0]),"r"(a[1]),"r"(a[2]),"r"(a[3]),"r"(b[0]),"r"(b[1]));
}
__device__ __forceinline__ float act_fn(float g, float u){
    g = fminf(g, FLIMIT);
    u = fminf(fmaxf(u, -FLIMIT), FLIMIT);
    float sig = __fdividef(1.f, 1.f + __expf(-ALPHA*g));
    return (u + 1.f) * (g * sig);
}
__device__ __forceinline__ void stsB(uint32_t addr, float4 lo, float4 hi, float s){
    uint32_t a = f2h2(lo.x*s, lo.y*s);
    uint32_t b = f2h2(lo.z*s, lo.w*s);
    uint32_t c = f2h2(hi.x*s, hi.y*s);
    uint32_t d = f2h2(hi.z*s, hi.w*s);
    asm volatile("st.shared.v4.b32 [%0], {%1,%2,%3,%4};" :: "r"(addr),"r"(a),"r"(b),"r"(c),"r"(d) : "memory");
}

// MMA inner block: 4 A-ldsm + 4 B-ldsm + 32 HMMA (warp tile 64x64)
#define MMA_KS(ks) do { \
    uint32_t af[4][4]; \
    _Pragma("unroll") \
    for (int m2=0;m2<4;m2++) \
        ldsm4(af[m2][0],af[m2][1],af[m2][2],af[m2][3], stg + lmA0 + m2*2304 + (ks)*32); \
    uint32_t bf[8][2]; \
    _Pragma("unroll") \
    for (int j=0;j<4;j++) \
        ldsm4(bf[2*j][0],bf[2*j][1],bf[2*j+1][0],bf[2*j+1][1], stg + lmB0 + j*2304 + (ks)*32); \
    _Pragma("unroll") \
    for (int nt=0;nt<8;nt++) \
        _Pragma("unroll") \
        for (int m2=0;m2<4;m2++) mma_f16(acc[m2][nt], af[m2], bf[nt]); \
} while(0)

// ---------------- K0: x -> fp16 ----------------
__global__ void prep_x_kernel(const float* __restrict__ x)
{
    const int i = blockIdx.x * blockDim.x + threadIdx.x;
    float4 v = *(const float4*)(x + (size_t)i*4);
    uint2 o;
    o.x = f2h2(v.x, v.y);
    o.y = f2h2(v.z, v.w);
    *(uint2*)(g_xh + (size_t)i*4) = o;
}

// ---------------- K1: router ----------------
__global__ void router_kernel(const float* __restrict__ x,
                              const float* __restrict__ rw,
                              const float* __restrict__ rb)
{
    __shared__ float sx[NH];
    __shared__ float slog[NEXP];
    const int t = blockIdx.x;
    for (int i = threadIdx.x; i < NH; i += blockDim.x)
        sx[i] = x[(size_t)t*NH + i];
    __syncthreads();
    const int w = threadIdx.x >> 5;
    const int lane = threadIdx.x & 31;
    const float* wr = rw + (size_t)w*NH;
    float s = 0.f;
    for (int i = lane; i < NH; i += 32) s += sx[i]*wr[i];
    #pragma unroll
    for (int o=16;o>0;o>>=1) s += __shfl_xor_sync(0xffffffffu, s, o);
    if (lane==0) slog[w] = s + rb[w];
    __syncthreads();
    if (threadIdx.x==0){
        float v[NEXP];
        #pragma unroll
        for (int e=0;e<NEXP;e++) v[e]=slog[e];
        int idx[NTOP]; float val[NTOP];
        #pragma unroll
        for (int k=0;k<NTOP;k++){
            int bi=0; float bv=v[0];
            #pragma unroll
            for (int e=1;e<NEXP;e++){ if (v[e]>bv){bv=v[e];bi=e;} }
            idx[k]=bi; val[k]=bv; v[bi]=-3.4e38f;
        }
        float mx=val[0], ssum=0.f, ev[NTOP];
        #pragma unroll
        for(int k=0;k<NTOP;k++){ ev[k]=expf(val[k]-mx); ssum+=ev[k]; }
        float inv = 1.f/ssum;
        #pragma unroll
        for(int k=0;k<NTOP;k++){
            g_tok_exp[t*NTOP+k]=idx[k];
            g_tok_w[t*NTOP+k]=ev[k]*inv;
        }
    }
}

// ---------------- K2: build per-expert token lists ----------------
__global__ void build_lists_kernel()
{
    __shared__ int sc[NEXP], so[NEXP], scur[NEXP];
    const int t = threadIdx.x;
    if (t < NEXP) sc[t]=0;
    __syncthreads();
    int ex[NTOP];
    #pragma unroll
    for (int k=0;k<NTOP;k++){ ex[k]=g_tok_exp[t*NTOP+k]; atomicAdd(&sc[ex[k]],1); }
    __syncthreads();
    if (t==0){
        int acc=0;
        for(int e=0;e<NEXP;e++){ so[e]=acc; acc+=sc[e]; }
    }
    __syncthreads();
    if (t<NEXP){ g_counts[t]=sc[t]; g_offsets[t]=so[t]; scur[t]=so[t]; }
    __syncthreads();
    #pragma unroll
    for (int k=0;k<NTOP;k++){
        int slot = atomicAdd(&scur[ex[k]],1);
        g_token_list[slot]=t;
        g_slot_of[t*NTOP+k]=slot;
    }
}

// ================= GEMM cores: 128 thr, 4 warps, warp tile 64x64 =================
// wm = (wid&1)*64, wn = (wid>>1)*64. 2-stage ring.
// A: 8 cp.async/thread. B: 8 segs/thread in 4 phases (2 in flight).

// ---------------- K3: gate+up GEMM + activation ----------------
// B rows 0-63: gate cols n0..n0+63; rows 64-127: up same cols.
__global__ void __launch_bounds__(128,2)
gateup_kernel(const float* __restrict__ gblk, const float* __restrict__ gscl,
              const float* __restrict__ gbia,
              const float* __restrict__ ublk, const float* __restrict__ uscl,
              const float* __restrict__ ubia)
{
    extern __shared__ float smf[];
    __shared__ int sTok[128];
    __shared__ float sGb[64], sUb[64];

    const int e   = blockIdx.y >> 3;
    const int mt  = blockIdx.y & 7;
    const int M   = g_counts[e];
    if (mt*128 >= M) return;
    const int Mrows = min(128, M - mt*128);
    const int off = g_offsets[e];
    const int n0  = blockIdx.x * 64;
    const int tid = threadIdx.x;
    const int wid = tid >> 5;
    const int lane = tid & 31;

    {
        int ml = mt*128 + tid; if (ml > M-1) ml = M-1;
        sTok[tid] = g_token_list[off + ml];
    }
    if (tid < 64){
        sGb[tid] = gbia[(size_t)e*NI + n0 + tid];
        sUb[tid] = ubia[(size_t)e*NI + n0 + tid];
    }
    __syncthreads();

    const uint32_t smemBase = smem_u32(smf);
    const int r0 = tid >> 3;
    const int s  = tid & 7;
    const int sh = s >> 2;

    const __half* srcA[8];
    #pragma unroll
    for (int j=0;j<8;j++)
        srcA[j] = g_xh + (size_t)sTok[r0 + 16*j]*NH + s*8;
    const uint32_t offA0 = (uint32_t)(r0*STRB + s*16);

    const float* pBg = gblk + ((size_t)e*NI + n0 + r0)*NH + s*8;
    const float* pBu = ublk + ((size_t)e*NI + n0 + r0)*NH + s*8;
    const float* pSg = gscl + ((size_t)e*NI + n0 + r0)*NBLKS;
    const float* pSu = uscl + ((size_t)e*NI + n0 + r0)*NBLKS;
    const uint32_t offB0 = (uint32_t)(ABYTES + r0*STRB + s*16);

    const int wm = (wid & 1) * 64;
    const int wn = (wid >> 1) * 64;
    const int fr = lane >> 2;
    const int fc = lane & 3;
    const bool active = (wm < Mrows);

    const uint32_t lmA0 = (uint32_t)((wm + (lane & 15))*STRB + (lane >> 4)*16);
    const uint32_t lmB0 = (uint32_t)(ABYTES + (wn + ((lane>>4)&1)*8 + (lane&7))*STRB + ((lane>>3)&1)*16);

    float acc[4][8][4];
    #pragma unroll
    for (int a=0;a<4;a++)
        #pragma unroll
        for (int b=0;b<8;b++)
            #pragma unroll
            for (int c=0;c<4;c++) acc[a][b][c]=0.f;

    // prologue: chunk 0
    {
        #pragma unroll
        for (int j=0;j<8;j++) cp16(smemBase + offA0 + j*2304, srcA[j]);
        cp_commit();
        #pragma unroll
        for (int j=0;j<8;j++){
            const float* bp = ((j<4)? pBg : pBu) + (j&3)*(16*NH);
            const float* sp = ((j<4)? pSg : pSu) + (j&3)*(16*NBLKS);
            float4 lo = *(const float4*)bp;
            float4 hi = *(const float4*)(bp+4);
            stsB(smemBase + offB0 + j*2304, lo, hi, sp[sh]);
        }
        cp_wait0();
    }
    __syncthreads();

    for (int kc=0; kc<NCH; kc++){
        const uint32_t stg = smemBase + (kc&1)*STAGEB;
        const uint32_t nst = smemBase + ((kc+1)&1)*STAGEB;
        const bool more = (kc+1 < NCH);
        if (more){
            const int ka = (kc+1)*64;
            #pragma unroll
            for (int j=0;j<8;j++) cp16(nst + offA0 + j*2304, srcA[j] + ka);
        }
        cp_commit();

        const int kb  = (kc+1)*64;
        const int ksc = 2*(kc+1) + sh;
        float4 lo[2][2], hi[2][2]; float sv[2][2];
        if (more){
            #pragma unroll
            for (int p=0;p<2;p++)
                #pragma unroll
                for (int q=0;q<2;q++){
                    const int j = 2*p+q;
                    const float* bp = ((j<4)? pBg : pBu) + (j&3)*(16*NH) + kb;
                    const float* sp = ((j<4)? pSg : pSu) + (j&3)*(16*NBLKS);
                    lo[p][q] = *(const float4*)bp; hi[p][q] = *(const float4*)(bp+4);
                    sv[p][q] = sp[ksc];
                }
        }
        if (active) MMA_KS(0);
        if (more){
            stsB(nst + offB0 + 0*2304, lo[0][0], hi[0][0], sv[0][0]);
            stsB(nst + offB0 + 1*2304, lo[0][1], hi[0][1], sv[0][1]);
            #pragma unroll
            for (int q=0;q<2;q++){
                const int j = 4+q;
                const float* bp = pBu + (j&3)*(16*NH) + kb;
                lo[0][q] = *(const float4*)bp; hi[0][q] = *(const float4*)(bp+4);
                sv[0][q] = (pSu + (j&3)*(16*NBLKS))[ksc];
            }
        }
        if (active) MMA_KS(1);
        if (more){
            stsB(nst + offB0 + 2*2304, lo[1][0], hi[1][0], sv[1][0]);
            stsB(nst + offB0 + 3*2304, lo[1][1], hi[1][1], sv[1][1]);
            #pragma unroll
            for (int q=0;q<2;q++){
                const int j = 6+q;
                const float* bp = pBu + (j&3)*(16*NH) + kb;
                lo[1][q] = *(const float4*)bp; hi[1][q] = *(const float4*)(bp+4);
                sv[1][q] = (pSu + (j&3)*(16*NBLKS))[ksc];
            }
        }
        if (active) MMA_KS(2);
        if (more){
            stsB(nst + offB0 + 4*2304, lo[0][0], hi[0][0], sv[0][0]);
            stsB(nst + offB0 + 5*2304, lo[0][1], hi[0][1], sv[0][1]);
        }
        if (active) MMA_KS(3);
        if (more){
            stsB(nst + offB0 + 6*2304, lo[1][0], hi[1][0], sv[1][0]);
            stsB(nst + offB0 + 7*2304, lo[1][1], hi[1][1], sv[1][1]);
        }
        cp_wait0();
        __syncthreads();
    }

    // epilogue: gate warps (wn==0) stash raw accs to G; up warps combine, write fp16 h.
    float* G = smf;   // 128*72*4 = 36864 B (stage 0)
    if (wn == 0 && active){
        #pragma unroll
        for (int m2=0;m2<4;m2++){
            #pragma unroll
            for (int nt=0;nt<8;nt++){
                const int rl = wm + m2*16 + fr;
                const int c  = nt*8 + fc*2;
                *(float2*)&G[rl*72 + c]     = make_float2(acc[m2][nt][0], acc[m2][nt][1]);
                *(float2*)&G[(rl+8)*72 + c] = make_float2(acc[m2][nt][2], acc[m2][nt][3]);
            }
        }
    }
    __syncthreads();
    if (wn == 64 && active){
        #pragma unroll
        for (int m2=0;m2<4;m2++){
            #pragma unroll
            for (int nt=0;nt<8;nt++){
                const int rl = wm + m2*16 + fr;
                const int cu = nt*8 + fc*2;
                const float gb0 = sGb[cu], gb1 = sGb[cu+1];
                const float ub0 = sUb[cu], ub1 = sUb[cu+1];
                if (rl < Mrows){
                    float2 gp = *(float2*)&G[rl*72 + cu];
                    float h0 = act_fn(gp.x+gb0, acc[m2][nt][0]+ub0);
                    float h1 = act_fn(gp.y+gb1, acc[m2][nt][1]+ub1);
                    *(uint32_t*)&g_hbuf[(size_t)(off + mt*128 + rl)*NI + n0 + cu] = f2h2(h0,h1);
                }
                if (rl+8 < Mrows){
                    float2 gp = *(float2*)&G[(rl+8)*72 + cu];
                    float h0 = act_fn(gp.x+gb0, acc[m2][nt][2]+ub0);
                    float h1 = act_fn(gp.y+gb1, acc[m2][nt][3]+ub1);
                    *(uint32_t*)&g_hbuf[(size_t)(off + mt*128 + rl+8)*NI + n0 + cu] = f2h2(h0,h1);
                }
            }
        }
    }
}

// ---------------- K4: down GEMM + bias ----------------
__global__ void __launch_bounds__(128,2)
down_kernel(const float* __restrict__ dblk, const float* __restrict__ dscl,
            const float* __restrict__ dbia)
{
    extern __shared__ float smf[];
    __shared__ float sDb[128];

    const int e   = blockIdx.y >> 3;
    const int mt  = blockIdx.y & 7;
    const int M   = g_counts[e];
    if (mt*128 >= M) return;
    const int Mrows = min(128, M - mt*128);
    const int off = g_offsets[e];
    const int n0  = blockIdx.x * 128;
    const int tid = threadIdx.x;
    const int wid = tid >> 5;
    const int lane = tid & 31;

    sDb[tid] = dbia[(size_t)e*NH + n0 + tid];
    __syncthreads();

    const uint32_t smemBase = smem_u32(smf);
    const int r0 = tid >> 3;
    const int s  = tid & 7;
    const int sh = s >> 2;

    const __half* srcA[8];
    #pragma unroll
    for (int j=0;j<8;j++){
        int ml = mt*128 + r0 + 16*j; if (ml > M-1) ml = M-1;
        srcA[j] = g_hbuf + (size_t)(off + ml)*NI + s*8;
    }
    const uint32_t offA0 = (uint32_t)(r0*STRB + s*16);

    const float* pBd = dblk + ((size_t)e*NH + n0 + r0)*NI + s*8;
    const float* pSd = dscl + ((size_t)e*NH + n0 + r0)*NBLKS;
    const uint32_t offB0 = (uint32_t)(ABYTES + r0*STRB + s*16);

    const int wm = (wid & 1) * 64;
    const int wn = (wid >> 1) * 64;
    const int fr = lane >> 2;
    const int fc = lane & 3;
    const bool active = (wm < Mrows);

    const uint32_t lmA0 = (uint32_t)((wm + (lane & 15))*STRB + (lane >> 4)*16);
    const uint32_t lmB0 = (uint32_t)(ABYTES + (wn + ((lane>>4)&1)*8 + (lane&7))*STRB + ((lane>>3)&1)*16);

    float acc[4][8][4];
    #pragma unroll
    for (int a=0;a<4;a++)
        #pragma unroll
        for (int b=0;b<8;b++)
            #pragma unroll
            for (int c=0;c<4;c++) acc[a][b][c]=0.f;

    {
        #pragma unroll
        for (int j=0;j<8;j++) cp16(smemBase + offA0 + j*2304, srcA[j]);
        cp_commit();
        #pragma unroll
        for (int j=0;j<8;j++){
            const float* bp = pBd + j*(16*NI);
            float4 lo = *(const float4*)bp;
            float4 hi = *(const float4*)(bp+4);
            stsB(smemBase + offB0 + j*2304, lo, hi, (pSd + j*(16*NBLKS))[sh]);
        }
        cp_wait0();
    }
    __syncthreads();

    for (int kc=0; kc<NCH; kc++){
        const uint32_t stg = smemBase + (kc&1)*STAGEB;
        const uint32_t nst = smemBase + ((kc+1)&1)*STAGEB;
        const bool more = (kc+1 < NCH);
        if (more){
            const int ka = (kc+1)*64;
            #pragma unroll
            for (int j=0;j<8;j++) cp16(nst + offA0 + j*2304, srcA[j] + ka);
        }
        cp_commit();

        const int kb  = (kc+1)*64;
        const int ksc = 2*(kc+1) + sh;
        float4 lo[2][2], hi[2][2]; float sv[2][2];
        if (more){
            #pragma unroll
            for (int p=0;p<2;p++)
                #pragma unroll
                for (int q=0;q<2;q++){
                    const int j = 2*p+q;
                    const float* bp = pBd + j*(16*NI) + kb;
                    lo[p][q] = *(const float4*)bp; hi[p][q] = *(const float4*)(bp+4);
                    sv[p][q] = (pSd + j*(16*NBLKS))[ksc];
                }
        }
        if (active) MMA_KS(0);
        if (more){
            stsB(nst + offB0 + 0*2304, lo[0][0], hi[0][0], sv[0][0]);
            stsB(nst + offB0 + 1*2304, lo[0][1], hi[0][1], sv[0][1]);
            #pragma unroll
            for (int q=0;q<2;q++){
                const int j = 4+q;
                const float* bp = pBd + j*(16*NI) + kb;
                lo[0][q] = *(const float4*)bp; hi[0][q] = *(const float4*)(bp+4);
                sv[0][q] = (pSd + j*(16*NBLKS))[ksc];
            }
        }
        if (active) MMA_KS(1);
        if (more){
            stsB(nst + offB0 + 2*2304, lo[1][0], hi[1][0], sv[1][0]);
            stsB(nst + offB0 + 3*2304, lo[1][1], hi[1][1], sv[1][1]);
            #pragma unroll
            for (int q=0;q<2;q++){
                const int j = 6+q;
                const float* bp = pBd + j*(16*NI) + kb;
                lo[1][q] = *(const float4*)bp; hi[1][q] = *(const float4*)(bp+4);
                sv[1][q] = (pSd + j*(16*NBLKS))[ksc];
            }
        }
        if (active) MMA_KS(2);
        if (more){
            stsB(nst + offB0 + 4*2304, lo[0][0], hi[0][0], sv[0][0]);
            stsB(nst + offB0 + 5*2304, lo[0][1], hi[0][1], sv[0][1]);
        }
        if (active) MMA_KS(3);
        if (more){
            stsB(nst + offB0 + 6*2304, lo[1][0], hi[1][0], sv[1][0]);
            stsB(nst + offB0 + 7*2304, lo[1][1], hi[1][1], sv[1][1]);
        }
        cp_wait0();
        __syncthreads();
    }

    if (active){
        #pragma unroll
        for (int m2=0;m2<4;m2++){
            #pragma unroll
            for (int nt=0;nt<8;nt++){
                const int rl = wm + m2*16 + fr;
                const int cg = wn + nt*8 + fc*2;
                const float b0 = sDb[cg], b1 = sDb[cg+1];
                if (rl < Mrows){
                    *(float2*)&g_obuf[(size_t)(off + mt*128 + rl)*NH + n0 + cg] =
                        make_float2(acc[m2][nt][0]+b0, acc[m2][nt][1]+b1);
                }
                if (rl+8 < Mrows){
                    *(float2*)&g_obuf[(size_t)(off + mt*128 + rl+8)*NH + n0 + cg] =
                        make_float2(acc[m2][nt][2]+b0, acc[m2][nt][3]+b1);
                }
            }
        }
    }
}

// ---------------- K5: weighted combine ----------------
__global__ void combine_kernel(float* __restrict__ out)
{
    const int t = blockIdx.x;
    int sl[NTOP]; float w[NTOP];
    #pragma unroll
    for (int k=0;k<NTOP;k++){ sl[k]=g_slot_of[t*NTOP+k]; w[k]=g_tok_w[t*NTOP+k]; }
    for (int i = threadIdx.x; i < NH/4; i += blockDim.x){
        float4 a = make_float4(0.f,0.f,0.f,0.f);
        #pragma unroll
        for (int k=0;k<NTOP;k++){
            float4 v = *(const float4*)&g_obuf[(size_t)sl[k]*NH + i*4];
            a.x += w[k]*v.x; a.y += w[k]*v.y; a.z += w[k]*v.z; a.w += w[k]*v.w;
        }
        *(float4*)&out[(size_t)t*NH + i*4] = a;
    }
}

// ---------------- launch ----------------
extern "C" void kernel_launch(void* const* d_in, const int* in_sizes, int n_in,
                              void* d_out, int out_size)
{
    const float* x    = (const float*)d_in[0];
    const float* rw   = (const float*)d_in[1];
    const float* rb   = (const float*)d_in[2];
    const float* gblk = (const float*)d_in[3];
    const float* gscl = (const float*)d_in[4];
    const float* gbia = (const float*)d_in[5];
    const float* ublk = (const float*)d_in[6];
    const float* uscl = (const float*)d_in[7];
    const float* ubia = (const float*)d_in[8];
    const float* dblk = (const float*)d_in[9];
    const float* dscl = (const float*)d_in[10];
    const float* dbia = (const float*)d_in[11];
    float* out = (float*)d_out;

    cudaFuncSetAttribute(gateup_kernel, cudaFuncAttributeMaxDynamicSharedMemorySize, DSMEM_BYTES);
    cudaFuncSetAttribute(down_kernel,   cudaFuncAttributeMaxDynamicSharedMemorySize, DSMEM_BYTES);

    prep_x_kernel<<<(NT*NH/4)/256, 256>>>(x);
    router_kernel<<<NT, 512>>>(x, rw, rb);
    build_lists_kernel<<<1, NT>>>();
    gateup_kernel<<<dim3(NI/64, NEXP*8), 128, DSMEM_BYTES>>>(gblk, gscl, gbia, ublk, uscl, ubia);
    down_kernel<<<dim3(NH/128, NEXP*8), 128, DSMEM_BYTES>>>(dblk, dscl, dbia);
    combine_kernel<<<NT, 256>>>(out);
}